// round 1
// baseline (speedup 1.0000x reference)
#include <cuda_runtime.h>

#define N_NODES 100000
#define E_EDGES 1600000
#define NE (E_EDGES + N_NODES)
#define IN_C 128
#define HH 128            // HEADS * HID
#define HEADS 4
#define HID 32
#define NC 16
#define NEG_SLOPE 0.2f

// ---------------- scratch (static device globals; no allocs allowed) ----------------
__device__ __align__(16) float g_h1[N_NODES * HH];     // layer1 linear output (gathered by edges)
__device__ __align__(16) float g_acc1[N_NODES * HH];   // layer1 aggregation accumulator / layer2 input
__device__ __align__(16) float g_as1[N_NODES * HEADS];
__device__ __align__(16) float g_ad1[N_NODES * HEADS];
__device__ __align__(16) float g_den1[N_NODES * HEADS];
__device__ __align__(16) float g_h2[N_NODES * NC];
__device__ __align__(16) float g_acc2[N_NODES * NC];
__device__ __align__(16) float g_as2[N_NODES];
__device__ __align__(16) float g_ad2[N_NODES];
__device__ __align__(16) float g_den2[N_NODES];

// ---------------- vector reductions (no-return atomics) ----------------
__device__ __forceinline__ void red_add4(float* addr, float a, float b, float c, float d) {
    asm volatile("red.global.add.v4.f32 [%0], {%1,%2,%3,%4};"
                 :: "l"(addr), "f"(a), "f"(b), "f"(c), "f"(d) : "memory");
}
__device__ __forceinline__ void red_add1(float* addr, float a) {
    asm volatile("red.global.add.f32 [%0], %1;" :: "l"(addr), "f"(a) : "memory");
}

// ---------------- init: zero accumulators/denominators ----------------
__global__ void k_init() {
    int i = blockIdx.x * blockDim.x + threadIdx.x;
    int stride = gridDim.x * blockDim.x;
    for (int j = i; j < N_NODES * HH; j += stride) g_acc1[j] = 0.f;
    for (int j = i; j < N_NODES * NC; j += stride) g_acc2[j] = 0.f;
    for (int j = i; j < N_NODES * HEADS; j += stride) g_den1[j] = 0.f;
    for (int j = i; j < N_NODES; j += stride) g_den2[j] = 0.f;
}

// ---------------- GEMM1: h1 = x @ W1  (100k x 128 @ 128 x 128) ----------------
// block = 128 threads (one output column each), 32 rows per block.
__global__ void k_gemm1(const float* __restrict__ x, const float* __restrict__ W1) {
    const int c = threadIdx.x;
    const int row0 = blockIdx.x * 32;
    __shared__ float xs[32][IN_C];
    #pragma unroll
    for (int r = 0; r < 32; r++)
        xs[r][c] = x[(size_t)(row0 + r) * IN_C + c];
    __syncthreads();

    float acc[32];
    #pragma unroll
    for (int r = 0; r < 32; r++) acc[r] = 0.f;

    for (int k = 0; k < IN_C; k += 4) {
        float w0 = W1[(k + 0) * HH + c];
        float w1 = W1[(k + 1) * HH + c];
        float w2 = W1[(k + 2) * HH + c];
        float w3 = W1[(k + 3) * HH + c];
        #pragma unroll
        for (int r = 0; r < 32; r++) {
            float4 xv = *reinterpret_cast<const float4*>(&xs[r][k]);
            acc[r] = fmaf(xv.x, w0, acc[r]);
            acc[r] = fmaf(xv.y, w1, acc[r]);
            acc[r] = fmaf(xv.z, w2, acc[r]);
            acc[r] = fmaf(xv.w, w3, acc[r]);
        }
    }
    #pragma unroll
    for (int r = 0; r < 32; r++)
        g_h1[(size_t)(row0 + r) * HH + c] = acc[r];
}

// ---------------- per-node attention coefficients layer1 ----------------
// one warp per node; lane l owns channels [4l, 4l+4); head = l>>3
__global__ void k_attn1(const float* __restrict__ att_src, const float* __restrict__ att_dst) {
    int warp = (blockIdx.x * blockDim.x + threadIdx.x) >> 5;
    int lane = threadIdx.x & 31;
    if (warp >= N_NODES) return;
    float4 hv = *reinterpret_cast<const float4*>(&g_h1[(size_t)warp * HH + lane * 4]);
    float4 as = *reinterpret_cast<const float4*>(&att_src[lane * 4]);
    float4 ad = *reinterpret_cast<const float4*>(&att_dst[lane * 4]);
    float ps = hv.x * as.x + hv.y * as.y + hv.z * as.z + hv.w * as.w;
    float pd = hv.x * ad.x + hv.y * ad.y + hv.z * ad.z + hv.w * ad.w;
    #pragma unroll
    for (int off = 4; off; off >>= 1) {
        ps += __shfl_down_sync(0xffffffffu, ps, off);
        pd += __shfl_down_sync(0xffffffffu, pd, off);
    }
    if ((lane & 7) == 0) {
        int head = lane >> 3;
        g_as1[warp * HEADS + head] = ps;
        g_ad1[warp * HEADS + head] = pd;
    }
}

// ---------------- edge pass layer1 (fused exp-weight + denom + weighted aggregate) ----
// one warp per edge; lane l handles 4 channels.
// Softmax max-subtraction is dropped: e = a_s + a_d is O(1)-bounded here, exp() cannot
// overflow, and alpha = exp(e)/sum exp(e) is mathematically identical.
__global__ void k_edge1(const int* __restrict__ ei) {
    int warp = (blockIdx.x * blockDim.x + threadIdx.x) >> 5;
    int lane = threadIdx.x & 31;
    if (warp >= NE) return;
    int s, d;
    if (warp < E_EDGES) { s = ei[warp]; d = ei[E_EDGES + warp]; }
    else { s = warp - E_EDGES; d = s; }

    float4 as = *reinterpret_cast<const float4*>(&g_as1[s * 4]);
    float4 ad = *reinterpret_cast<const float4*>(&g_ad1[d * 4]);
    float4 e;
    e.x = as.x + ad.x; e.y = as.y + ad.y; e.z = as.z + ad.z; e.w = as.w + ad.w;
    // leaky_relu(v) == max(v, 0.2*v) for slope in (0,1)
    e.x = fmaxf(e.x, NEG_SLOPE * e.x);
    e.y = fmaxf(e.y, NEG_SLOPE * e.y);
    e.z = fmaxf(e.z, NEG_SLOPE * e.z);
    e.w = fmaxf(e.w, NEG_SLOPE * e.w);
    float4 w;
    w.x = __expf(e.x); w.y = __expf(e.y); w.z = __expf(e.z); w.w = __expf(e.w);

    if (lane == 0) red_add4(&g_den1[d * 4], w.x, w.y, w.z, w.w);

    float wl = (lane < 8) ? w.x : (lane < 16) ? w.y : (lane < 24) ? w.z : w.w;
    float4 hv = *reinterpret_cast<const float4*>(&g_h1[(size_t)s * HH + lane * 4]);
    red_add4(&g_acc1[(size_t)d * HH + lane * 4], hv.x * wl, hv.y * wl, hv.z * wl, hv.w * wl);
}

// ---------------- mid: out1 = acc/denom + b1, then ELU; in place into g_acc1 ----------
__global__ void k_mid(const float* __restrict__ b1) {
    int i = blockIdx.x * blockDim.x + threadIdx.x;
    if (i >= N_NODES * HH) return;
    int n = i >> 7;
    int k = i & 127;
    float v = g_acc1[i] / g_den1[n * HEADS + (k >> 5)] + b1[k];
    g_acc1[i] = v > 0.f ? v : expm1f(v);
}

// ---------------- GEMM2: h2 = elu_out @ W2 (128 -> 16), fused a_s2/a_d2 ----------------
// block = 256 threads: 16 nodes x 16 output classes.
__global__ void k_gemm2(const float* __restrict__ W2,
                        const float* __restrict__ att_src2,
                        const float* __restrict__ att_dst2) {
    __shared__ float hs[16][IN_C];
    __shared__ float w2s[IN_C * NC];
    int tid = threadIdx.x;
    int row0 = blockIdx.x * 16;
    for (int j = tid; j < IN_C * NC; j += 256) w2s[j] = W2[j];
    for (int j = tid; j < 16 * IN_C; j += 256) {
        int r = j >> 7, k = j & 127;
        hs[r][k] = g_acc1[(size_t)(row0 + r) * IN_C + k];
    }
    __syncthreads();

    int nl = tid >> 4, c = tid & 15;
    int n = row0 + nl;
    float acc = 0.f;
    #pragma unroll 4
    for (int k = 0; k < IN_C; k++)
        acc = fmaf(hs[nl][k], w2s[k * NC + c], acc);
    g_h2[n * NC + c] = acc;

    float ps = acc * att_src2[c];
    float pd = acc * att_dst2[c];
    #pragma unroll
    for (int off = 8; off; off >>= 1) {
        ps += __shfl_down_sync(0xffffffffu, ps, off);
        pd += __shfl_down_sync(0xffffffffu, pd, off);
    }
    if (c == 0) { g_as2[n] = ps; g_ad2[n] = pd; }
}

// ---------------- edge pass layer2 (H=1, C=16): 4 lanes per edge ----------------
__global__ void k_edge2(const int* __restrict__ ei) {
    int t = blockIdx.x * blockDim.x + threadIdx.x;
    int i = t >> 2;
    int j = t & 3;
    if (i >= NE) return;
    int s, d;
    if (i < E_EDGES) { s = ei[i]; d = ei[E_EDGES + i]; }
    else { s = i - E_EDGES; d = s; }
    float e = g_as2[s] + g_ad2[d];
    e = fmaxf(e, NEG_SLOPE * e);
    float w = __expf(e);
    if (j == 0) red_add1(&g_den2[d], w);
    float4 hv = *reinterpret_cast<const float4*>(&g_h2[s * NC + j * 4]);
    red_add4(&g_acc2[d * NC + j * 4], hv.x * w, hv.y * w, hv.z * w, hv.w * w);
}

// ---------------- final: out = acc2/denom2 + b2 ----------------
__global__ void k_final(const float* __restrict__ b2, float* __restrict__ out) {
    int i = blockIdx.x * blockDim.x + threadIdx.x;
    if (i >= N_NODES * NC) return;
    out[i] = g_acc2[i] / g_den2[i >> 4] + b2[i & 15];
}

extern "C" void kernel_launch(void* const* d_in, const int* in_sizes, int n_in,
                              void* d_out, int out_size) {
    const float* x        = (const float*)d_in[0];
    const int*   ei       = (const int*)  d_in[1];
    const float* W1       = (const float*)d_in[2];
    const float* att_src1 = (const float*)d_in[3];
    const float* att_dst1 = (const float*)d_in[4];
    const float* b1       = (const float*)d_in[5];
    const float* W2       = (const float*)d_in[6];
    const float* att_src2 = (const float*)d_in[7];
    const float* att_dst2 = (const float*)d_in[8];
    const float* b2       = (const float*)d_in[9];
    float* out = (float*)d_out;

    k_init<<<2048, 256>>>();
    k_gemm1<<<N_NODES / 32, 128>>>(x, W1);
    k_attn1<<<(N_NODES * 32 + 255) / 256, 256>>>(att_src1, att_dst1);
    k_edge1<<<(int)(((long long)NE * 32 + 255) / 256), 256>>>(ei);
    k_mid<<<(N_NODES * HH + 255) / 256, 256>>>(b1);
    k_gemm2<<<N_NODES / 16, 256>>>(W2, att_src2, att_dst2);
    k_edge2<<<(NE * 4 + 255) / 256, 256>>>(ei);
    k_final<<<(N_NODES * NC + 255) / 256, 256>>>(b2, out);
}

// round 2
// speedup vs baseline: 1.1184x; 1.1184x over previous
#include <cuda_runtime.h>

#define N_NODES 100000
#define E_EDGES 1600000
#define NE (E_EDGES + N_NODES)   // edges + self loops
#define IN_C 128
#define HH 128            // HEADS * HID
#define HEADS 4
#define HID 32
#define NC 16
#define NEG_SLOPE 0.2f

// ---------------- scratch (static device globals; no allocs allowed) ----------------
__device__ __align__(16) float g_h1[N_NODES * HH];     // layer1 linear output
__device__ __align__(16) float g_acc1[N_NODES * HH];   // layer1 output (post ELU) = layer2 input
__device__ __align__(16) float g_as1[N_NODES * HEADS];
__device__ __align__(16) float g_ad1[N_NODES * HEADS];
__device__ __align__(16) float g_h2[N_NODES * NC];
__device__ __align__(16) float g_as2[N_NODES];
__device__ __align__(16) float g_ad2[N_NODES];

// CSR scratch
__device__ int g_deg[N_NODES];
__device__ int g_off[N_NODES + 1];
__device__ int g_cur[N_NODES];
__device__ int g_csr[NE];          // src ids grouped by dst

// ---------------- CSR build ----------------
__global__ void k_zero_deg() {
    int i = blockIdx.x * blockDim.x + threadIdx.x;
    if (i < N_NODES) g_deg[i] = 0;
}

__global__ void k_hist(const int* __restrict__ ei) {
    int i = blockIdx.x * blockDim.x + threadIdx.x;
    if (i >= NE) return;
    int d = (i < E_EDGES) ? ei[E_EDGES + i] : (i - E_EDGES);
    atomicAdd(&g_deg[d], 1);
}

// single-block exclusive scan over 100k degrees (1024 threads x ~98 elems)
__global__ void k_scan() {
    __shared__ int sums[1024];
    const int tid = threadIdx.x;
    const int CHUNK = (N_NODES + 1023) / 1024;   // 98
    const int base = tid * CHUNK;
    int s = 0;
    for (int i = 0; i < CHUNK; i++) {
        int idx = base + i;
        if (idx < N_NODES) s += g_deg[idx];
    }
    sums[tid] = s;
    __syncthreads();
    int total = s;
    for (int off = 1; off < 1024; off <<= 1) {
        int t = (tid >= off) ? sums[tid - off] : 0;
        __syncthreads();
        sums[tid] += t;
        __syncthreads();
    }
    int run = sums[tid] - total;   // exclusive prefix
    for (int i = 0; i < CHUNK; i++) {
        int idx = base + i;
        if (idx < N_NODES) {
            g_off[idx] = run;
            g_cur[idx] = run;
            run += g_deg[idx];
        }
    }
    if (tid == 1023) g_off[N_NODES] = run;
}

__global__ void k_fill(const int* __restrict__ ei) {
    int i = blockIdx.x * blockDim.x + threadIdx.x;
    if (i >= NE) return;
    int s, d;
    if (i < E_EDGES) { s = ei[i]; d = ei[E_EDGES + i]; }
    else { s = i - E_EDGES; d = s; }
    int pos = atomicAdd(&g_cur[d], 1);
    g_csr[pos] = s;
}

// ---------------- GEMM1: h1 = x @ W1  (100k x 128 @ 128 x 128) ----------------
__global__ void k_gemm1(const float* __restrict__ x, const float* __restrict__ W1) {
    const int c = threadIdx.x;
    const int row0 = blockIdx.x * 32;
    __shared__ float xs[32][IN_C];
    #pragma unroll
    for (int r = 0; r < 32; r++)
        xs[r][c] = x[(size_t)(row0 + r) * IN_C + c];
    __syncthreads();

    float acc[32];
    #pragma unroll
    for (int r = 0; r < 32; r++) acc[r] = 0.f;

    for (int k = 0; k < IN_C; k += 4) {
        float w0 = W1[(k + 0) * HH + c];
        float w1 = W1[(k + 1) * HH + c];
        float w2 = W1[(k + 2) * HH + c];
        float w3 = W1[(k + 3) * HH + c];
        #pragma unroll
        for (int r = 0; r < 32; r++) {
            float4 xv = *reinterpret_cast<const float4*>(&xs[r][k]);
            acc[r] = fmaf(xv.x, w0, acc[r]);
            acc[r] = fmaf(xv.y, w1, acc[r]);
            acc[r] = fmaf(xv.z, w2, acc[r]);
            acc[r] = fmaf(xv.w, w3, acc[r]);
        }
    }
    #pragma unroll
    for (int r = 0; r < 32; r++)
        g_h1[(size_t)(row0 + r) * HH + c] = acc[r];
}

// ---------------- per-node attention coefficients layer1 ----------------
__global__ void k_attn1(const float* __restrict__ att_src, const float* __restrict__ att_dst) {
    int warp = (blockIdx.x * blockDim.x + threadIdx.x) >> 5;
    int lane = threadIdx.x & 31;
    if (warp >= N_NODES) return;
    float4 hv = *reinterpret_cast<const float4*>(&g_h1[(size_t)warp * HH + lane * 4]);
    float4 as = *reinterpret_cast<const float4*>(&att_src[lane * 4]);
    float4 ad = *reinterpret_cast<const float4*>(&att_dst[lane * 4]);
    float ps = hv.x * as.x + hv.y * as.y + hv.z * as.z + hv.w * as.w;
    float pd = hv.x * ad.x + hv.y * ad.y + hv.z * ad.z + hv.w * ad.w;
    #pragma unroll
    for (int off = 4; off; off >>= 1) {
        ps += __shfl_down_sync(0xffffffffu, ps, off);
        pd += __shfl_down_sync(0xffffffffu, pd, off);
    }
    if ((lane & 7) == 0) {
        int head = lane >> 3;
        g_as1[warp * HEADS + head] = ps;
        g_ad1[warp * HEADS + head] = pd;
    }
}

// ---------------- layer1 aggregation: warp per dst node, CSR order, no atomics ----
// lane l owns channels [4l,4l+4), head = l>>3. Fused softmax-normalize + bias + ELU.
// (max-subtraction dropped: e is O(1)-bounded, exp cannot overflow)
__global__ void k_agg1(const float* __restrict__ b1) {
    int d = (blockIdx.x * blockDim.x + threadIdx.x) >> 5;
    int lane = threadIdx.x & 31;
    if (d >= N_NODES) return;
    const int head = lane >> 3;
    const float ad_h = g_ad1[d * HEADS + head];
    int j = g_off[d];
    const int end = g_off[d + 1];

    float4 acc = make_float4(0.f, 0.f, 0.f, 0.f);
    float den = 0.f;

    // 2-way unrolled main loop for gather MLP
    for (; j + 2 <= end; j += 2) {
        int s0 = g_csr[j], s1 = g_csr[j + 1];
        float e0 = g_as1[s0 * HEADS + head] + ad_h;
        float e1 = g_as1[s1 * HEADS + head] + ad_h;
        float4 h0 = *reinterpret_cast<const float4*>(&g_h1[(size_t)s0 * HH + lane * 4]);
        float4 h1 = *reinterpret_cast<const float4*>(&g_h1[(size_t)s1 * HH + lane * 4]);
        e0 = fmaxf(e0, NEG_SLOPE * e0);
        e1 = fmaxf(e1, NEG_SLOPE * e1);
        float w0 = __expf(e0), w1 = __expf(e1);
        den += w0 + w1;
        acc.x = fmaf(w0, h0.x, acc.x); acc.y = fmaf(w0, h0.y, acc.y);
        acc.z = fmaf(w0, h0.z, acc.z); acc.w = fmaf(w0, h0.w, acc.w);
        acc.x = fmaf(w1, h1.x, acc.x); acc.y = fmaf(w1, h1.y, acc.y);
        acc.z = fmaf(w1, h1.z, acc.z); acc.w = fmaf(w1, h1.w, acc.w);
    }
    for (; j < end; j++) {
        int s = g_csr[j];
        float e = g_as1[s * HEADS + head] + ad_h;
        float4 hv = *reinterpret_cast<const float4*>(&g_h1[(size_t)s * HH + lane * 4]);
        e = fmaxf(e, NEG_SLOPE * e);
        float w = __expf(e);
        den += w;
        acc.x = fmaf(w, hv.x, acc.x); acc.y = fmaf(w, hv.y, acc.y);
        acc.z = fmaf(w, hv.z, acc.z); acc.w = fmaf(w, hv.w, acc.w);
    }

    float inv = 1.f / den;   // den > 0 guaranteed by self loop
    float4 bv = *reinterpret_cast<const float4*>(&b1[lane * 4]);
    float4 v;
    v.x = acc.x * inv + bv.x; v.y = acc.y * inv + bv.y;
    v.z = acc.z * inv + bv.z; v.w = acc.w * inv + bv.w;
    v.x = v.x > 0.f ? v.x : expm1f(v.x);
    v.y = v.y > 0.f ? v.y : expm1f(v.y);
    v.z = v.z > 0.f ? v.z : expm1f(v.z);
    v.w = v.w > 0.f ? v.w : expm1f(v.w);
    *reinterpret_cast<float4*>(&g_acc1[(size_t)d * HH + lane * 4]) = v;
}

// ---------------- GEMM2: h2 = elu_out @ W2 (128 -> 16), fused a_s2/a_d2 ----------------
__global__ void k_gemm2(const float* __restrict__ W2,
                        const float* __restrict__ att_src2,
                        const float* __restrict__ att_dst2) {
    __shared__ float hs[16][IN_C];
    __shared__ float w2s[IN_C * NC];
    int tid = threadIdx.x;
    int row0 = blockIdx.x * 16;
    for (int j = tid; j < IN_C * NC; j += 256) w2s[j] = W2[j];
    for (int j = tid; j < 16 * IN_C; j += 256) {
        int r = j >> 7, k = j & 127;
        hs[r][k] = g_acc1[(size_t)(row0 + r) * IN_C + k];
    }
    __syncthreads();

    int nl = tid >> 4, c = tid & 15;
    int n = row0 + nl;
    float acc = 0.f;
    #pragma unroll 4
    for (int k = 0; k < IN_C; k++)
        acc = fmaf(hs[nl][k], w2s[k * NC + c], acc);
    g_h2[n * NC + c] = acc;

    float ps = acc * att_src2[c];
    float pd = acc * att_dst2[c];
    #pragma unroll
    for (int off = 8; off; off >>= 1) {
        ps += __shfl_down_sync(0xffffffffu, ps, off);
        pd += __shfl_down_sync(0xffffffffu, pd, off);
    }
    if (c == 0) { g_as2[n] = ps; g_ad2[n] = pd; }
}

// ---------------- layer2 aggregation: 16 lanes per dst node, CSR, writes d_out ----
__global__ void k_agg2(const float* __restrict__ b2, float* __restrict__ out) {
    int t = blockIdx.x * blockDim.x + threadIdx.x;
    int d = t >> 4;
    int c = t & 15;
    if (d >= N_NODES) return;
    const float ad = g_ad2[d];
    int j = g_off[d];
    const int end = g_off[d + 1];
    float acc = 0.f, den = 0.f;
    for (; j + 2 <= end; j += 2) {
        int s0 = g_csr[j], s1 = g_csr[j + 1];
        float e0 = g_as2[s0] + ad;
        float e1 = g_as2[s1] + ad;
        float h0 = g_h2[s0 * NC + c];
        float h1 = g_h2[s1 * NC + c];
        e0 = fmaxf(e0, NEG_SLOPE * e0);
        e1 = fmaxf(e1, NEG_SLOPE * e1);
        float w0 = __expf(e0), w1 = __expf(e1);
        den += w0 + w1;
        acc = fmaf(w0, h0, acc);
        acc = fmaf(w1, h1, acc);
    }
    for (; j < end; j++) {
        int s = g_csr[j];
        float e = g_as2[s] + ad;
        float h = g_h2[s * NC + c];
        e = fmaxf(e, NEG_SLOPE * e);
        float w = __expf(e);
        den += w;
        acc = fmaf(w, h, acc);
    }
    out[d * NC + c] = acc / den + b2[c];
}

extern "C" void kernel_launch(void* const* d_in, const int* in_sizes, int n_in,
                              void* d_out, int out_size) {
    const float* x        = (const float*)d_in[0];
    const int*   ei       = (const int*)  d_in[1];
    const float* W1       = (const float*)d_in[2];
    const float* att_src1 = (const float*)d_in[3];
    const float* att_dst1 = (const float*)d_in[4];
    const float* b1       = (const float*)d_in[5];
    const float* W2       = (const float*)d_in[6];
    const float* att_src2 = (const float*)d_in[7];
    const float* att_dst2 = (const float*)d_in[8];
    const float* b2       = (const float*)d_in[9];
    float* out = (float*)d_out;

    // CSR build (overlappable with gemm1 on the same stream order; serialized is fine)
    k_zero_deg<<<(N_NODES + 255) / 256, 256>>>();
    k_hist<<<(NE + 255) / 256, 256>>>(ei);
    k_scan<<<1, 1024>>>();
    k_fill<<<(NE + 255) / 256, 256>>>(ei);

    k_gemm1<<<N_NODES / 32, 128>>>(x, W1);
    k_attn1<<<(N_NODES * 32 + 255) / 256, 256>>>(att_src1, att_dst1);
    k_agg1<<<(N_NODES * 32 + 255) / 256, 256>>>(b1);

    k_gemm2<<<N_NODES / 16, 256>>>(W2, att_src2, att_dst2);
    k_agg2<<<(N_NODES * 16 + 255) / 256, 256>>>(b2, out);
}